// round 11
// baseline (speedup 1.0000x reference)
#include <cuda_runtime.h>
#include <cstddef>

#define HDIM  512
#define TDIM  1024
#define TPB   256            // threads per block
#define NW    (TPB / 32)     // 8 warps
#define CH2   (TDIM / TPB)   // 4 t-values per thread
#define HPT   (HDIM / TPB)   // 2 h-values per thread
#define PKCAP (HDIM + 64)    // compacted + padding
#define TWO_PI_F 6.283185307179586476925286766559f
#define CINF  3.402823466e38f
#define FULLM 0xffffffffu

// Sticky violation flag bits (zero at load; set via atomicOr only).
// bit0 = W_h not identity, bit1 = b_x nonzero.
__device__ int g_flags;
// Arrival counter; reset to 0 by the last block each launch.
__device__ int g_done;

__device__ __forceinline__ float warp_sum(float v) {
    #pragma unroll
    for (int o = 16; o; o >>= 1) v += __shfl_xor_sync(FULLM, v, o);
    return v;
}

// ---------------------------------------------------------------------------
// Single launch. One block per batch element:
//  speculative fast path -> W_h/b_x checks -> done-counter; the LAST
//  finisher (checks complete) recomputes everything iff a flag tripped.
//
// Fast math (W_h==I, b_x==0): h_t = X_t*wx - M_t,
//   M_t = min(a, wx*Cmin_t) [wx>=0] / min(a, wx*Cmax_t), a = -h0.
// Split: R_t = Rpos(Cmin_t) [over wx>=0] + Rneg(Cmax_t) [over wx<0];
// Rpos changes only at prefix-min records, Rneg only at prefix-max records.
// out[t] = X_t*<wx,wk> - Rpos - Rneg + b_out.
// ---------------------------------------------------------------------------
__global__ void __launch_bounds__(TPB) rnn_kernel(
    const float* __restrict__ x,       // [B, T]
    const float* __restrict__ theta0,  // [B]
    const float* __restrict__ W_h,     // [H, H]
    const float* __restrict__ W_x,     // [H]
    const float* __restrict__ b_x,     // [H]
    const float* __restrict__ W_h0,    // [H]
    const float* __restrict__ b_h0,    // [H]
    const float* __restrict__ W_out,   // [2, H]
    const float* __restrict__ b_out,   // [2]
    float* __restrict__ out,           // [T+1, B, 2]
    int B, int T, int H, int fastOK)
{
    __shared__ float  sRecCmin[TDIM + 1];   // cmin-record values
    __shared__ float  sRecCmax[TDIM + 1];   // cmax-record values
    __shared__ float2 sRp[TDIM + 1];        // Rpos per cmin-record
    __shared__ float2 sRn[TDIM + 1];        // Rneg per cmax-record
    __shared__ float4 sPk[PKCAP];           // sign-compacted {wx, a, w0, w1}
    __shared__ float  sS[NW], sMn[NW], sMx[NW];
    __shared__ int    sScrA[NW], sScrB[NW];
    __shared__ int    snrec, snpos;
    __shared__ float2 sDred[NW];
    __shared__ int    sLast;
    __shared__ float2 sred[NW];
    __shared__ float  hbuf[2][HDIM];

    const int b    = blockIdx.x;
    const int tid  = threadIdx.x;
    const int lane = tid & 31;
    const int warp = tid >> 5;
    const float INF = __int_as_float(0x7f800000);

    // ---- Prefetch: fast-path operands AND this block's W_h check element ----
    const int n  = H * H;
    const int n4 = n >> 2;
    const float4* W4 = reinterpret_cast<const float4*>(W_h);
    const int i40 = b * TPB + tid;
    float4 wv = make_float4(0.f, 0.f, 0.f, 0.f);
    if (i40 < n4) wv = W4[i40];              // consumed AFTER the fast path

    float th = 0.f, b0 = 0.f, b1 = 0.f;
    float rwx[HPT], rw0[HPT], rw1[HPT], ra[HPT];
    float4 xv = make_float4(0.f, 0.f, 0.f, 0.f);
    const int doFast = fastOK && (b < B);
    if (doFast) {
        th = theta0[b] * TWO_PI_F;
        b0 = b_out[0];
        b1 = b_out[1];
        xv = reinterpret_cast<const float4*>(x + (size_t)b * TDIM)[tid];
        #pragma unroll
        for (int r = 0; r < HPT; r++) {
            const int h = r * TPB + tid;
            rwx[r] = W_x[h];
            rw0[r] = W_out[h];
            rw1[r] = W_out[HDIM + h];
            ra[r]  = -fmaf(th, W_h0[h], b_h0[h]);   // a = -h0
        }
    }

    if (doFast) {
        // ---- Fused triple scan: (sum, prefix-min, prefix-max) ----
        float lx[CH2];
        float Xoff, Omn, Omx;
        {
            lx[0] = xv.x;
            lx[1] = lx[0] + xv.y;
            lx[2] = lx[1] + xv.z;
            lx[3] = lx[2] + xv.w;
            float mn = lx[0], mx = lx[0];
            #pragma unroll
            for (int j = 1; j < CH2; j++) {
                mn = fminf(mn, lx[j]);
                mx = fmaxf(mx, lx[j]);
            }
            float S = lx[CH2 - 1], m = mn, M = mx;
            #pragma unroll
            for (int o = 1; o < 32; o <<= 1) {
                const float sL = __shfl_up_sync(FULLM, S, o);
                const float mL = __shfl_up_sync(FULLM, m, o);
                const float ML = __shfl_up_sync(FULLM, M, o);
                if (lane >= o) {
                    m = fminf(mL, sL + m);
                    M = fmaxf(ML, sL + M);
                    S = sL + S;
                }
            }
            float eS = __shfl_up_sync(FULLM, S, 1);
            float eMn = __shfl_up_sync(FULLM, m, 1);
            float eMx = __shfl_up_sync(FULLM, M, 1);
            if (lane == 0) { eS = 0.f; eMn = CINF; eMx = -CINF; }

            if (lane == 31) { sS[warp] = S; sMn[warp] = m; sMx[warp] = M; }
            __syncthreads();

            float aS = (lane < NW) ? sS[lane] : 0.f;
            float am = (lane < NW) ? sMn[lane] : CINF;
            float aM = (lane < NW) ? sMx[lane] : -CINF;
            #pragma unroll
            for (int o = 1; o < NW; o <<= 1) {
                const float sL = __shfl_up_sync(FULLM, aS, o);
                const float mL = __shfl_up_sync(FULLM, am, o);
                const float ML = __shfl_up_sync(FULLM, aM, o);
                if (lane >= o) {
                    am = fminf(mL, sL + am);
                    aM = fmaxf(ML, sL + aM);
                    aS = sL + aS;
                }
            }
            const int src = (warp > 0) ? (warp - 1) : 0;
            float bS  = __shfl_sync(FULLM, aS, src);
            float bMn = __shfl_sync(FULLM, am, src);
            float bMx = __shfl_sync(FULLM, aM, src);
            if (warp == 0) { bS = 0.f; bMn = CINF; bMx = -CINF; }

            Xoff = bS + eS;
            Omn  = fminf(bMn, bS + eMn);
            Omx  = fmaxf(bMx, bS + eMx);
        }

        // per-element prefix values + split record flags (registers)
        float cmn[CH2], cmx[CH2];
        int   recp[CH2], recn[CH2];
        {
            float pm = Omn, pM = Omx;
            #pragma unroll
            for (int j = 0; j < CH2; j++) {
                lx[j] += Xoff;
                cmn[j] = fminf(pm, lx[j]);
                cmx[j] = fmaxf(pM, lx[j]);
                recp[j] = (cmn[j] < pm);
                recn[j] = (cmx[j] > pM);
                pm = cmn[j]; pM = cmx[j];
            }
        }

        // ---- ONE packed scan: records (cA: recp | recn<<16) + pos count (cB)
        int ridp[CH2], ridn[CH2];
        {
            int lcA[CH2];
            int cA = 0;
            #pragma unroll
            for (int j = 0; j < CH2; j++) {
                cA += recp[j] + (recn[j] << 16);
                lcA[j] = cA;
            }
            int cB = 0;
            #pragma unroll
            for (int r = 0; r < HPT; r++) cB += (rwx[r] >= 0.f);

            int wA = cA, wB = cB;
            #pragma unroll
            for (int o = 1; o < 32; o <<= 1) {
                const int uA = __shfl_up_sync(FULLM, wA, o);
                const int uB = __shfl_up_sync(FULLM, wB, o);
                if (lane >= o) { wA += uA; wB += uB; }
            }
            int eA = __shfl_up_sync(FULLM, wA, 1);
            int eB = __shfl_up_sync(FULLM, wB, 1);
            if (lane == 0) { eA = 0; eB = 0; }
            if (lane == 31) { sScrA[warp] = wA; sScrB[warp] = wB; }
            __syncthreads();

            int aA = (lane < NW) ? sScrA[lane] : 0;
            int aB = (lane < NW) ? sScrB[lane] : 0;
            #pragma unroll
            for (int o = 1; o < NW; o <<= 1) {
                const int uA = __shfl_up_sync(FULLM, aA, o);
                const int uB = __shfl_up_sync(FULLM, aB, o);
                if (lane >= o) { aA += uA; aB += uB; }
            }
            const int src = (warp > 0) ? (warp - 1) : 0;
            int bA = __shfl_sync(FULLM, aA, src);
            int bB = __shfl_sync(FULLM, aB, src);
            if (warp == 0) { bA = 0; bB = 0; }
            if (warp == NW - 1 && lane == 31) { snrec = bA + wA; snpos = bB + wB; }

            const int offA = bA + eA;
            #pragma unroll
            for (int j = 0; j < CH2; j++) {
                const int packed = lcA[j] + offA;
                ridp[j] = packed & 0xffff;
                ridn[j] = packed >> 16;
                if (recp[j]) sRecCmin[ridp[j]] = cmn[j];
                if (recn[j]) sRecCmax[ridn[j]] = cmx[j];
            }

            // ---- sign compaction scatter (needs snpos -> sync first) ----
            __syncthreads();
            const int npos    = snpos;
            const int posPad  = (npos + 31) & ~31;
            const int nneg    = HDIM - npos;
            const int negPad  = (nneg + 31) & ~31;
            const int posExcl = bB + eB;
            int pe = posExcl;
            int ne = posPad + 2 * tid - posExcl;
            #pragma unroll
            for (int r = 0; r < HPT; r++) {
                const float4 v = make_float4(rwx[r], ra[r], rw0[r], rw1[r]);
                if (rwx[r] >= 0.f) sPk[pe++] = v;
                else               sPk[ne++] = v;
            }
            // zero padding (contributes exactly 0; NaN-safe vs +-INF)
            if (tid < 32) {
                if (npos + tid < posPad)
                    sPk[npos + tid] = make_float4(0.f, 0.f, 0.f, 0.f);
            } else if (tid < 64) {
                const int i = tid - 32;
                if (nneg + i < negPad)
                    sPk[posPad + nneg + i] = make_float4(0.f, 0.f, 0.f, 0.f);
            }
        }
        if (tid == 0) {
            sRecCmin[0] = INF;    // sentinel: fmin(a, wx*INF)=a (wx>=0, NaN-safe)
            sRecCmax[0] = -INF;   // sentinel: fmin(a, wx*-INF)=a (wx<0)
        }
        __syncthreads();

        // ---- task loop: one record-half per warp per iteration ----
        const int npos    = snpos;
        const int posPad  = (npos + 31) & ~31;
        const int negPad  = (HDIM - npos + 31) & ~31;
        const int nrp     = snrec & 0xffff;
        const int nrn     = snrec >> 16;
        const int ntask   = nrp + nrn + 2;
        const int posIt   = posPad >> 5;
        const int negIt   = negPad >> 5;

        for (int q = warp; q < ntask; q += NW) {
            const bool isPos = (q <= nrp);
            const int  base  = isPos ? 0 : posPad;
            const int  iters = isPos ? posIt : negIt;
            const float c    = isPos ? sRecCmin[q] : sRecCmax[q - nrp - 1];
            float p0 = 0.f, p1 = 0.f;
            #pragma unroll 4
            for (int i = 0; i < iters; i++) {
                const float4 pk = sPk[base + i * 32 + lane];
                const float m = fminf(pk.y, pk.x * c);
                p0 = fmaf(m, pk.z, p0);
                p1 = fmaf(m, pk.w, p1);
            }
            #pragma unroll
            for (int o = 16; o; o >>= 1) {
                p0 += __shfl_xor_sync(FULLM, p0, o);
                p1 += __shfl_xor_sync(FULLM, p1, o);
            }
            if (lane == 0) {
                if (isPos) sRp[q] = make_float2(p0, p1);
                else       sRn[q - nrp - 1] = make_float2(p0, p1);
            }
        }

        // ---- dots <wx,w0>, <wx,w1> ----
        {
            float d0 = 0.f, d2 = 0.f;
            #pragma unroll
            for (int r = 0; r < HPT; r++) {
                d0 = fmaf(rwx[r], rw0[r], d0);
                d2 = fmaf(rwx[r], rw1[r], d2);
            }
            d0 = warp_sum(d0);
            d2 = warp_sum(d2);
            if (lane == 0) sDred[warp] = make_float2(d0, d2);
        }
        __syncthreads();   // orders sRp/sRn writes before the reads below

        float D0, D2;
        {
            float v0 = 0.f, v1 = 0.f;
            if (lane < NW) { const float2 d = sDred[lane]; v0 = d.x; v1 = d.y; }
            #pragma unroll
            for (int o = NW / 2; o; o >>= 1) {
                v0 += __shfl_xor_sync(FULLM, v0, o);
                v1 += __shfl_xor_sync(FULLM, v1, o);
            }
            D0 = __shfl_sync(FULLM, v0, 0);
            D2 = __shfl_sync(FULLM, v1, 0);
        }

        // ---- emit outputs (speculative) ----
        #pragma unroll
        for (int j = 0; j < CH2; j++) {
            const int t = tid * CH2 + j + 1;
            const float2 Rp = sRp[ridp[j]];
            const float2 Rn = sRn[ridn[j]];
            float2 o;
            o.x = fmaf(lx[j], D0, b0) - Rp.x - Rn.x;
            o.y = fmaf(lx[j], D2, b1) - Rp.y - Rn.y;
            reinterpret_cast<float2*>(out)[(size_t)t * B + b] = o;
        }
        if (tid == 0) {
            const float2 Rp0 = sRp[0];
            const float2 Rn0 = sRn[0];
            reinterpret_cast<float2*>(out)[b] =
                make_float2(b0 - Rp0.x - Rn0.x, b1 - Rp0.y - Rn0.y);
        }
    }

    // ---- Checks (consume prefetched wv) ----
    {
        if (i40 < n4) {
            const int e = i40 << 2;
            const int r = e / H;
            const int c = e - r * H;
            const float e0 = (c     == r) ? 1.f : 0.f;
            const float e1 = (c + 1 == r) ? 1.f : 0.f;
            const float e2 = (c + 2 == r) ? 1.f : 0.f;
            const float e3 = (c + 3 == r) ? 1.f : 0.f;
            if (wv.x != e0 || wv.y != e1 || wv.z != e2 || wv.w != e3)
                atomicOr(&g_flags, 1);
        }
        for (int i4 = i40 + gridDim.x * TPB; i4 < n4; i4 += gridDim.x * TPB) {
            const float4 v = W4[i4];
            const int e = i4 << 2;
            const int r = e / H;
            const int c = e - r * H;
            const float e0 = (c     == r) ? 1.f : 0.f;
            const float e1 = (c + 1 == r) ? 1.f : 0.f;
            const float e2 = (c + 2 == r) ? 1.f : 0.f;
            const float e3 = (c + 3 == r) ? 1.f : 0.f;
            if (v.x != e0 || v.y != e1 || v.z != e2 || v.w != e3)
                atomicOr(&g_flags, 1);
        }
        if (b == 0) {
            for (int i = (n4 << 2) + tid; i < n; i += TPB) {
                const int r = i / H, c = i - r * H;
                if (W_h[i] != ((r == c) ? 1.f : 0.f)) atomicOr(&g_flags, 1);
            }
            for (int i = tid; i < H; i += TPB)
                if (b_x[i] != 0.0f) atomicOr(&g_flags, 2);
        }
    }

    // ---- Arrival: last finisher decides ----
    __syncthreads();
    if (tid == 0) {
        __threadfence();                       // publish this block's atomicOrs
        const int old = atomicAdd(&g_done, 1);
        sLast = (old == (int)gridDim.x - 1);
    }
    __syncthreads();
    if (!sLast) return;                        // common case: exit, no waiting

    if (tid == 0) g_done = 0;                  // reset for the next replay
    __threadfence();
    const int flags = *(volatile int*)&g_flags;
    if (fastOK && flags == 0) return;          // speculation valid

    // ================= Fallback: this ONE block recomputes everything ======
    const int nid = (flags & 1) || !fastOK;
    const float fb0 = b_out[0], fb1 = b_out[1];

    for (int bb = 0; bb < B; bb++) {
        const float fth = theta0[bb] * TWO_PI_F;

        float wx[HPT], bx[HPT], w0[HPT], w1[HPT], h[HPT];
        #pragma unroll
        for (int r = 0; r < HPT; r++) {
            const int hh = r * TPB + tid;
            if (hh < H) {
                wx[r] = W_x[hh];
                bx[r] = b_x[hh];
                w0[r] = W_out[hh];
                w1[r] = W_out[H + hh];
                h[r]  = fmaf(fth, W_h0[hh], b_h0[hh]);
                hbuf[0][hh] = h[r];
            } else {
                wx[r] = bx[r] = w0[r] = w1[r] = h[r] = 0.f;
            }
        }
        __syncthreads();

        // t = 0 row
        {
            float p0 = 0.f, p1 = 0.f;
            #pragma unroll
            for (int r = 0; r < HPT; r++) {
                p0 = fmaf(h[r], w0[r], p0);
                p1 = fmaf(h[r], w1[r], p1);
            }
            p0 = warp_sum(p0); p1 = warp_sum(p1);
            if (lane == 0) sred[warp] = make_float2(p0, p1);
            __syncthreads();
            if (tid == 0) {
                float o0 = fb0, o1 = fb1;
                for (int w = 0; w < NW; w++) { o0 += sred[w].x; o1 += sred[w].y; }
                reinterpret_cast<float2*>(out)[bb] = make_float2(o0, o1);
            }
            __syncthreads();
        }

        int cur = 0;
        for (int t = 0; t < T; t++) {
            const float xt = __ldg(&x[(size_t)bb * T + t]);
            float acc[HPT];
            #pragma unroll
            for (int r = 0; r < HPT; r++) acc[r] = fmaf(xt, wx[r], bx[r]);

            if (!nid) {
                #pragma unroll
                for (int r = 0; r < HPT; r++) acc[r] += h[r];
            } else {
                const float* hs = hbuf[cur];
                #pragma unroll
                for (int r = 0; r < HPT; r++) {
                    const int hh = r * TPB + tid;
                    if (hh < H) {
                        const float* Wr = W_h + (size_t)hh * H;
                        for (int k = 0; k < H; k++)
                            acc[r] = fmaf(Wr[k], hs[k], acc[r]);
                    }
                }
            }
            float p0 = 0.f, p1 = 0.f;
            #pragma unroll
            for (int r = 0; r < HPT; r++) {
                const int hh = r * TPB + tid;
                h[r] = fmaxf(acc[r], 0.f);
                if (hh < H) {
                    if (nid) hbuf[1 - cur][hh] = h[r];
                    p0 = fmaf(h[r], w0[r], p0);
                    p1 = fmaf(h[r], w1[r], p1);
                }
            }
            p0 = warp_sum(p0); p1 = warp_sum(p1);
            if (lane == 0) sred[warp] = make_float2(p0, p1);
            __syncthreads();
            if (tid == 0) {
                float o0 = fb0, o1 = fb1;
                for (int w = 0; w < NW; w++) { o0 += sred[w].x; o1 += sred[w].y; }
                reinterpret_cast<float2*>(out)[(size_t)(t + 1) * B + bb] =
                    make_float2(o0, o1);
            }
            __syncthreads();
            cur ^= 1;
        }
        __syncthreads();
    }
}

// ---------------------------------------------------------------------------
extern "C" void kernel_launch(void* const* d_in, const int* in_sizes, int n_in,
                              void* d_out, int out_size)
{
    const float* x     = (const float*)d_in[0];
    const float* th0   = (const float*)d_in[1];
    const float* W_h   = (const float*)d_in[2];
    const float* W_x   = (const float*)d_in[3];
    const float* b_x   = (const float*)d_in[4];
    const float* W_h0  = (const float*)d_in[5];
    const float* b_h0  = (const float*)d_in[6];
    const float* W_out = (const float*)d_in[7];
    const float* b_out = (const float*)d_in[8];

    const int H   = in_sizes[4];           // 512
    const int NAV = in_sizes[8] / 2;       // 1
    const int B   = in_sizes[1] / NAV;     // 256
    const int I   = in_sizes[3] / H;       // 1
    const int T   = in_sizes[0] / (B * I); // 1024

    const int fastOK = (H == HDIM && T == TDIM) ? 1 : 0;

    rnn_kernel<<<B, TPB>>>(x, th0, W_h, W_x, b_x, W_h0, b_h0,
                           W_out, b_out, (float*)d_out, B, T, H, fastOK);
}

// round 12
// speedup vs baseline: 1.4168x; 1.4168x over previous
#include <cuda_runtime.h>
#include <cstddef>

#define HDIM  512
#define TDIM  1024
#define TPB   256            // threads per block
#define NW    (TPB / 32)     // 8 warps
#define CH2   (TDIM / TPB)   // 4 t-values per thread
#define HPT   (HDIM / TPB)   // 2 h-values per thread
#define TWO_PI_F 6.283185307179586476925286766559f
#define CINF  3.402823466e38f
#define FULLM 0xffffffffu

// Sticky violation flag bits (zero at load; set via atomicOr only).
// bit0 = W_h not identity, bit1 = b_x nonzero.
__device__ int g_flags;
// Arrival counter; reset to 0 by the last block each launch.
__device__ int g_done;

__device__ __forceinline__ float warp_sum(float v) {
    #pragma unroll
    for (int o = 16; o; o >>= 1) v += __shfl_xor_sync(FULLM, v, o);
    return v;
}

// ---------------------------------------------------------------------------
// Single launch, no grid barrier. One block per batch element:
//   1) prefetch (incl. this block's W_h check element),
//   2) independent work first (sPk staging + dots) in the LDG shadow,
//   3) speculative fast closed form + output stores,
//   4) W_h / b_x checks (consume prefetched data), sticky flags,
//   5) atomicAdd on done-counter; every block exits except the LAST finisher,
//      which (checks complete) recomputes everything iff a flag tripped.
//
// Fast math (W_h==I, b_x==0): h_t = X_t*wx - M_t,
//   M_t = min(a, wx*Cmin_t) [wx>=0] / min(a, wx*Cmax_t), a = -h0,
// X = cumsum(x); R_t = sum_h M_t*wk changes only at prefix-record times.
// out[t] = X_t*<wx,wk> - R_t + b_out.
// ---------------------------------------------------------------------------
__global__ void __launch_bounds__(TPB) rnn_kernel(
    const float* __restrict__ x,       // [B, T]
    const float* __restrict__ theta0,  // [B]
    const float* __restrict__ W_h,     // [H, H]
    const float* __restrict__ W_x,     // [H]
    const float* __restrict__ b_x,     // [H]
    const float* __restrict__ W_h0,    // [H]
    const float* __restrict__ b_h0,    // [H]
    const float* __restrict__ W_out,   // [2, H]
    const float* __restrict__ b_out,   // [2]
    float* __restrict__ out,           // [T+1, B, 2]
    int B, int T, int H, int fastOK)
{
    __shared__ float  sRecCmin[TDIM + 1];
    __shared__ float  sRecCmax[TDIM + 1];
    __shared__ float2 sRrec[TDIM + 1];
    __shared__ float4 sPk[HDIM];            // {wx, a, w0, w1}
    __shared__ float  sS[NW], sMn[NW], sMx[NW];
    __shared__ int    sScrI[NW];
    __shared__ int    snrec;
    __shared__ float2 sDred[NW];
    __shared__ int    sLast;
    __shared__ float2 sred[NW];
    __shared__ float  hbuf[2][HDIM];

    const int b    = blockIdx.x;
    const int tid  = threadIdx.x;
    const int lane = tid & 31;
    const int warp = tid >> 5;
    const float INF = __int_as_float(0x7f800000);

    // ---- Prefetch: fast-path operands AND this block's W_h check element ----
    const int n  = H * H;
    const int n4 = n >> 2;
    const float4* W4 = reinterpret_cast<const float4*>(W_h);
    const int i40 = b * TPB + tid;
    float4 wv = make_float4(0.f, 0.f, 0.f, 0.f);
    if (i40 < n4) wv = W4[i40];              // consumed AFTER the fast path

    float th = 0.f, b0 = 0.f, b1 = 0.f;
    float rwx[HPT], rw0[HPT], rw1[HPT], ra[HPT];
    float4 xv = make_float4(0.f, 0.f, 0.f, 0.f);
    const int doFast = fastOK && (b < B);
    if (doFast) {
        th = theta0[b] * TWO_PI_F;
        b0 = b_out[0];
        b1 = b_out[1];
        xv = reinterpret_cast<const float4*>(x + (size_t)b * TDIM)[tid];
        #pragma unroll
        for (int r = 0; r < HPT; r++) {
            const int h = r * TPB + tid;
            rwx[r] = W_x[h];
            rw0[r] = W_out[h];
            rw1[r] = W_out[HDIM + h];
            ra[r]  = -fmaf(th, W_h0[h], b_h0[h]);   // a = -h0
        }
    }

    if (doFast) {
        // ---- Independent work first (hidden under LDG latency) ----
        // stage packed per-h data {wx, a, w0, w1}
        #pragma unroll
        for (int r = 0; r < HPT; r++) {
            const int h = r * TPB + tid;
            sPk[h] = make_float4(rwx[r], ra[r], rw0[r], rw1[r]);
        }
        // dot partials <wx,w0>, <wx,w1>
        {
            float d0 = 0.f, d2 = 0.f;
            #pragma unroll
            for (int r = 0; r < HPT; r++) {
                d0 = fmaf(rwx[r], rw0[r], d0);
                d2 = fmaf(rwx[r], rw1[r], d2);
            }
            d0 = warp_sum(d0);
            d2 = warp_sum(d2);
            if (lane == 0) sDred[warp] = make_float2(d0, d2);
        }

        // ---- Fused triple scan: (sum, prefix-min, prefix-max) ----
        float lx[CH2];
        float Xoff, Omn, Omx;
        {
            lx[0] = xv.x;
            lx[1] = lx[0] + xv.y;
            lx[2] = lx[1] + xv.z;
            lx[3] = lx[2] + xv.w;
            float mn = lx[0], mx = lx[0];
            #pragma unroll
            for (int j = 1; j < CH2; j++) {
                mn = fminf(mn, lx[j]);
                mx = fmaxf(mx, lx[j]);
            }
            float S = lx[CH2 - 1], m = mn, M = mx;
            #pragma unroll
            for (int o = 1; o < 32; o <<= 1) {
                const float sL = __shfl_up_sync(FULLM, S, o);
                const float mL = __shfl_up_sync(FULLM, m, o);
                const float ML = __shfl_up_sync(FULLM, M, o);
                if (lane >= o) {
                    m = fminf(mL, sL + m);
                    M = fmaxf(ML, sL + M);
                    S = sL + S;
                }
            }
            // thread-exclusive within warp
            float eS = __shfl_up_sync(FULLM, S, 1);
            float eMn = __shfl_up_sync(FULLM, m, 1);
            float eMx = __shfl_up_sync(FULLM, M, 1);
            if (lane == 0) { eS = 0.f; eMn = CINF; eMx = -CINF; }

            if (lane == 31) { sS[warp] = S; sMn[warp] = m; sMx[warp] = M; }
            __syncthreads();   // covers sPk + sDred + sS/sMn/sMx

            // parallel combine: shfl monoid scan over warp aggregates
            float aS = (lane < NW) ? sS[lane] : 0.f;
            float am = (lane < NW) ? sMn[lane] : CINF;
            float aM = (lane < NW) ? sMx[lane] : -CINF;
            #pragma unroll
            for (int o = 1; o < NW; o <<= 1) {
                const float sL = __shfl_up_sync(FULLM, aS, o);
                const float mL = __shfl_up_sync(FULLM, am, o);
                const float ML = __shfl_up_sync(FULLM, aM, o);
                if (lane >= o) {
                    am = fminf(mL, sL + am);
                    aM = fmaxf(ML, sL + aM);
                    aS = sL + aS;
                }
            }
            const int src = (warp > 0) ? (warp - 1) : 0;
            float bS  = __shfl_sync(FULLM, aS, src);
            float bMn = __shfl_sync(FULLM, am, src);
            float bMx = __shfl_sync(FULLM, aM, src);
            if (warp == 0) { bS = 0.f; bMn = CINF; bMx = -CINF; }

            Xoff = bS + eS;
            Omn  = fminf(bMn, bS + eMn);
            Omx  = fmaxf(bMx, bS + eMx);
        }

        // per-element prefix values + record flags (registers)
        float cmn[CH2], cmx[CH2];
        int   rec[CH2], rid[CH2];
        {
            float pm = Omn, pM = Omx;
            #pragma unroll
            for (int j = 0; j < CH2; j++) {
                lx[j] += Xoff;
                cmn[j] = fminf(pm, lx[j]);
                cmx[j] = fmaxf(pM, lx[j]);
                rec[j] = (cmn[j] < pm) || (cmx[j] > pM);
                pm = cmn[j]; pM = cmx[j];
            }
        }

        // ---- record-count scan -> segment ids ----
        {
            int lc[CH2];
            int c = 0;
            #pragma unroll
            for (int j = 0; j < CH2; j++) { c += rec[j]; lc[j] = c; }
            int wc = c;
            #pragma unroll
            for (int o = 1; o < 32; o <<= 1) {
                const int u = __shfl_up_sync(FULLM, wc, o);
                if (lane >= o) wc += u;
            }
            int ec = __shfl_up_sync(FULLM, wc, 1);
            if (lane == 0) ec = 0;
            if (lane == 31) sScrI[warp] = wc;
            __syncthreads();
            int av = (lane < NW) ? sScrI[lane] : 0;
            #pragma unroll
            for (int o = 1; o < NW; o <<= 1) {
                const int u = __shfl_up_sync(FULLM, av, o);
                if (lane >= o) av += u;
            }
            const int src = (warp > 0) ? (warp - 1) : 0;
            int boff = __shfl_sync(FULLM, av, src);
            if (warp == 0) boff = 0;
            if (warp == NW - 1 && lane == 31) snrec = boff + wc;
            const int off = boff + ec;
            #pragma unroll
            for (int j = 0; j < CH2; j++) {
                rid[j] = lc[j] + off;
                if (rec[j]) {
                    sRecCmin[rid[j]] = cmn[j];
                    sRecCmax[rid[j]] = cmx[j];
                }
            }
        }
        if (tid == 0) {
            sRecCmin[0] = INF;    // sentinel: min(a,wx*INF)=a (NaN-safe wx==0)
            sRecCmax[0] = -INF;
        }
        __syncthreads();          // record values visible to all warps

        // ---- R at each record: 4 records per warp per round ----
        const int nrec = snrec;
        for (int r0 = warp; r0 <= nrec; r0 += 4 * NW) {
            int   rr[4];
            int   hv[4];
            float cmv[4], cxv[4];
            #pragma unroll
            for (int k = 0; k < 4; k++) {
                rr[k] = r0 + k * NW;
                hv[k] = (rr[k] <= nrec);
                cmv[k] = hv[k] ? sRecCmin[rr[k]] : 0.f;
                cxv[k] = hv[k] ? sRecCmax[rr[k]] : 0.f;
            }
            float p0[4] = {0.f, 0.f, 0.f, 0.f};
            float p1[4] = {0.f, 0.f, 0.f, 0.f};
            #pragma unroll
            for (int i = 0; i < HDIM / 32; i++) {
                const float4 pk = sPk[i * 32 + lane];
                const float wx = pk.x, a = pk.y, w0 = pk.z, w1 = pk.w;
                #pragma unroll
                for (int k = 0; k < 4; k++) {
                    const float m = fminf(a, wx * ((wx >= 0.f) ? cmv[k] : cxv[k]));
                    p0[k] = fmaf(m, w0, p0[k]);
                    p1[k] = fmaf(m, w1, p1[k]);
                }
            }
            #pragma unroll
            for (int o = 16; o; o >>= 1) {
                #pragma unroll
                for (int k = 0; k < 4; k++) {
                    p0[k] += __shfl_xor_sync(FULLM, p0[k], o);
                    p1[k] += __shfl_xor_sync(FULLM, p1[k], o);
                }
            }
            if (lane == 0) {
                #pragma unroll
                for (int k = 0; k < 4; k++)
                    if (hv[k]) sRrec[rr[k]] = make_float2(p0[k], p1[k]);
            }
        }
        __syncthreads();   // orders sRrec writes before the reads below

        float D0, D2;
        {
            float v0 = 0.f, v1 = 0.f;
            if (lane < NW) { const float2 d = sDred[lane]; v0 = d.x; v1 = d.y; }
            #pragma unroll
            for (int o = NW / 2; o; o >>= 1) {
                v0 += __shfl_xor_sync(FULLM, v0, o);
                v1 += __shfl_xor_sync(FULLM, v1, o);
            }
            D0 = __shfl_sync(FULLM, v0, 0);
            D2 = __shfl_sync(FULLM, v1, 0);
        }

        // ---- emit outputs (speculative) ----
        #pragma unroll
        for (int j = 0; j < CH2; j++) {
            const int t = tid * CH2 + j + 1;
            const float2 R = sRrec[rid[j]];
            float2 o;
            o.x = fmaf(lx[j], D0, b0) - R.x;
            o.y = fmaf(lx[j], D2, b1) - R.y;
            reinterpret_cast<float2*>(out)[(size_t)t * B + b] = o;
        }
        if (tid == 0) {
            const float2 R0 = sRrec[0];
            reinterpret_cast<float2*>(out)[b] = make_float2(b0 - R0.x, b1 - R0.y);
        }
    }

    // ---- Checks (consume prefetched wv; off the front of the critical path) --
    {
        if (i40 < n4) {
            const int e = i40 << 2;
            const int r = e / H;
            const int c = e - r * H;
            const float e0 = (c     == r) ? 1.f : 0.f;
            const float e1 = (c + 1 == r) ? 1.f : 0.f;
            const float e2 = (c + 2 == r) ? 1.f : 0.f;
            const float e3 = (c + 3 == r) ? 1.f : 0.f;
            if (wv.x != e0 || wv.y != e1 || wv.z != e2 || wv.w != e3)
                atomicOr(&g_flags, 1);
        }
        for (int i4 = i40 + gridDim.x * TPB; i4 < n4; i4 += gridDim.x * TPB) {
            const float4 v = W4[i4];
            const int e = i4 << 2;
            const int r = e / H;
            const int c = e - r * H;
            const float e0 = (c     == r) ? 1.f : 0.f;
            const float e1 = (c + 1 == r) ? 1.f : 0.f;
            const float e2 = (c + 2 == r) ? 1.f : 0.f;
            const float e3 = (c + 3 == r) ? 1.f : 0.f;
            if (v.x != e0 || v.y != e1 || v.z != e2 || v.w != e3)
                atomicOr(&g_flags, 1);
        }
        if (b == 0) {
            for (int i = (n4 << 2) + tid; i < n; i += TPB) {
                const int r = i / H, c = i - r * H;
                if (W_h[i] != ((r == c) ? 1.f : 0.f)) atomicOr(&g_flags, 1);
            }
            for (int i = tid; i < H; i += TPB)
                if (b_x[i] != 0.0f) atomicOr(&g_flags, 2);
        }
    }

    // ---- Arrival: last finisher decides ----
    __syncthreads();
    if (tid == 0) {
        __threadfence();                       // publish this block's atomicOrs
        const int old = atomicAdd(&g_done, 1);
        sLast = (old == (int)gridDim.x - 1);
    }
    __syncthreads();
    if (!sLast) return;                        // common case: exit, no waiting

    if (tid == 0) g_done = 0;                  // reset for the next replay
    __threadfence();
    const int flags = *(volatile int*)&g_flags;
    if (fastOK && flags == 0) return;          // speculation valid

    // ================= Fallback: this ONE block recomputes everything ======
    const int nid = (flags & 1) || !fastOK;
    const float fb0 = b_out[0], fb1 = b_out[1];

    for (int bb = 0; bb < B; bb++) {
        const float fth = theta0[bb] * TWO_PI_F;

        float wx[HPT], bx[HPT], w0[HPT], w1[HPT], h[HPT];
        #pragma unroll
        for (int r = 0; r < HPT; r++) {
            const int hh = r * TPB + tid;
            if (hh < H) {
                wx[r] = W_x[hh];
                bx[r] = b_x[hh];
                w0[r] = W_out[hh];
                w1[r] = W_out[H + hh];
                h[r]  = fmaf(fth, W_h0[hh], b_h0[hh]);
                hbuf[0][hh] = h[r];
            } else {
                wx[r] = bx[r] = w0[r] = w1[r] = h[r] = 0.f;
            }
        }
        __syncthreads();

        // t = 0 row
        {
            float p0 = 0.f, p1 = 0.f;
            #pragma unroll
            for (int r = 0; r < HPT; r++) {
                p0 = fmaf(h[r], w0[r], p0);
                p1 = fmaf(h[r], w1[r], p1);
            }
            p0 = warp_sum(p0); p1 = warp_sum(p1);
            if (lane == 0) sred[warp] = make_float2(p0, p1);
            __syncthreads();
            if (tid == 0) {
                float o0 = fb0, o1 = fb1;
                for (int w = 0; w < NW; w++) { o0 += sred[w].x; o1 += sred[w].y; }
                reinterpret_cast<float2*>(out)[bb] = make_float2(o0, o1);
            }
            __syncthreads();
        }

        int cur = 0;
        for (int t = 0; t < T; t++) {
            const float xt = __ldg(&x[(size_t)bb * T + t]);
            float acc[HPT];
            #pragma unroll
            for (int r = 0; r < HPT; r++) acc[r] = fmaf(xt, wx[r], bx[r]);

            if (!nid) {
                #pragma unroll
                for (int r = 0; r < HPT; r++) acc[r] += h[r];
            } else {
                const float* hs = hbuf[cur];
                #pragma unroll
                for (int r = 0; r < HPT; r++) {
                    const int hh = r * TPB + tid;
                    if (hh < H) {
                        const float* Wr = W_h + (size_t)hh * H;
                        for (int k = 0; k < H; k++)
                            acc[r] = fmaf(Wr[k], hs[k], acc[r]);
                    }
                }
            }
            float p0 = 0.f, p1 = 0.f;
            #pragma unroll
            for (int r = 0; r < HPT; r++) {
                const int hh = r * TPB + tid;
                h[r] = fmaxf(acc[r], 0.f);
                if (hh < H) {
                    if (nid) hbuf[1 - cur][hh] = h[r];
                    p0 = fmaf(h[r], w0[r], p0);
                    p1 = fmaf(h[r], w1[r], p1);
                }
            }
            p0 = warp_sum(p0); p1 = warp_sum(p1);
            if (lane == 0) sred[warp] = make_float2(p0, p1);
            __syncthreads();
            if (tid == 0) {
                float o0 = fb0, o1 = fb1;
                for (int w = 0; w < NW; w++) { o0 += sred[w].x; o1 += sred[w].y; }
                reinterpret_cast<float2*>(out)[(size_t)(t + 1) * B + bb] =
                    make_float2(o0, o1);
            }
            __syncthreads();
            cur ^= 1;
        }
        __syncthreads();
    }
}

// ---------------------------------------------------------------------------
extern "C" void kernel_launch(void* const* d_in, const int* in_sizes, int n_in,
                              void* d_out, int out_size)
{
    const float* x     = (const float*)d_in[0];
    const float* th0   = (const float*)d_in[1];
    const float* W_h   = (const float*)d_in[2];
    const float* W_x   = (const float*)d_in[3];
    const float* b_x   = (const float*)d_in[4];
    const float* W_h0  = (const float*)d_in[5];
    const float* b_h0  = (const float*)d_in[6];
    const float* W_out = (const float*)d_in[7];
    const float* b_out = (const float*)d_in[8];

    const int H   = in_sizes[4];           // 512
    const int NAV = in_sizes[8] / 2;       // 1
    const int B   = in_sizes[1] / NAV;     // 256
    const int I   = in_sizes[3] / H;       // 1
    const int T   = in_sizes[0] / (B * I); // 1024

    const int fastOK = (H == HDIM && T == TDIM) ? 1 : 0;

    rnn_kernel<<<B, TPB>>>(x, th0, W_h, W_x, b_x, W_h0, b_h0,
                           W_out, b_out, (float*)d_out, B, T, H, fastOK);
}